// round 7
// baseline (speedup 1.0000x reference)
#include <cuda_runtime.h>

#define BB 4096
#define TT 512
#define HH 32

typedef unsigned long long u64;

__device__ __forceinline__ u64 pk2(float lo, float hi) {
    u64 r; asm("mov.b64 %0, {%1,%2};" : "=l"(r) : "f"(lo), "f"(hi)); return r;
}
__device__ __forceinline__ void unpk2(u64 v, float& a, float& b) {
    asm("mov.b64 {%0,%1}, %2;" : "=f"(a), "=f"(b) : "l"(v));
}
// Packed f32x2 FMA / ADD (Blackwell full-rate; ptxas never auto-fuses these)
__device__ __forceinline__ u64 ffma2(u64 a, u64 b, u64 c) {
    u64 d; asm("fma.rn.f32x2 %0, %1, %2, %3;" : "=l"(d) : "l"(a), "l"(b), "l"(c));
    return d;
}
__device__ __forceinline__ u64 fadd2(u64 a, u64 b) {
    u64 d; asm("add.rn.f32x2 %0, %1, %2;" : "=l"(d) : "l"(a), "l"(b));
    return d;
}

// tanh with 2*log2(e) pre-folded: tanh(v) = 1 - 2*rcp(ex2(v') + 1)
__device__ __forceinline__ float tanh_scaled(float vp) {
    float e; asm("ex2.approx.f32 %0, %1;" : "=f"(e) : "f"(vp));
    float r; asm("rcp.approx.f32 %0, %1;" : "=f"(r) : "f"(e + 1.0f));
    return fmaf(-2.0f, r, 1.0f);
}

// FFMA block for batch bi, phase p: L0(p+1) + L1(p) accumulators.
// Biases and the x-term are folded into accumulator initialization.
#define FFMA_FULL(bi)                                                   \
    do {                                                                \
        a0[bi]  = pk2(fmaf(wx0, xv[bi], bb0), 0.f);                     \
        a0b[bi] = pk2(0.f, 0.f);                                        \
        a1[bi]  = pk2(bb1, 0.f);                                        \
        a1b[bi] = pk2(0.f, 0.f);                                        \
        _Pragma("unroll")                                               \
        for (int i = 0; i < 8; i++) {                                   \
            ulonglong2 v = ((const ulonglong2*)sh0[bi])[i];             \
            a0[bi]  = ffma2(w0[2*i],    v.x, a0[bi]);                   \
            a0b[bi] = ffma2(w0[2*i+1],  v.y, a0b[bi]);                  \
            a1[bi]  = ffma2(wi1[2*i],   v.x, a1[bi]);                   \
            a1b[bi] = ffma2(wi1[2*i+1], v.y, a1b[bi]);                  \
        }                                                               \
        _Pragma("unroll")                                               \
        for (int i = 0; i < 8; i++) {                                   \
            ulonglong2 u = ((const ulonglong2*)sh1[bi])[i];             \
            a1[bi]  = ffma2(wh1[2*i],   u.x, a1[bi]);                   \
            a1b[bi] = ffma2(wh1[2*i+1], u.y, a1b[bi]);                  \
        }                                                               \
    } while (0)

// FFMA block for the final phase: L1(TT-1) only (must not clobber sh0).
#define FFMA_L1(bi)                                                     \
    do {                                                                \
        a1[bi]  = pk2(bb1, 0.f);                                        \
        a1b[bi] = pk2(0.f, 0.f);                                        \
        _Pragma("unroll")                                               \
        for (int i = 0; i < 8; i++) {                                   \
            ulonglong2 v = ((const ulonglong2*)sh0[bi])[i];             \
            a1[bi]  = ffma2(wi1[2*i],   v.x, a1[bi]);                   \
            a1b[bi] = ffma2(wi1[2*i+1], v.y, a1b[bi]);                  \
        }                                                               \
        _Pragma("unroll")                                               \
        for (int i = 0; i < 8; i++) {                                   \
            ulonglong2 u = ((const ulonglong2*)sh1[bi])[i];             \
            a1[bi]  = ffma2(wh1[2*i],   u.x, a1[bi]);                   \
            a1b[bi] = ffma2(wh1[2*i+1], u.y, a1b[bi]);                  \
        }                                                               \
    } while (0)

#define FINISH_FULL(bi)                                                 \
    do {                                                                \
        float lo, hi;                                                   \
        unpk2(fadd2(a0[bi], a0b[bi]), lo, hi);                          \
        sh0[bi][j] = tanh_scaled(lo + hi);       /* h0'(p+1) */         \
        unpk2(fadd2(a1[bi], a1b[bi]), lo, hi);                          \
        h1n[bi] = tanh_scaled(lo + hi);          /* h1'(p)   */         \
        sh1[bi][j] = h1n[bi];                                           \
    } while (0)

#define FINISH_L1(bi)                                                   \
    do {                                                                \
        float lo, hi;                                                   \
        unpk2(fadd2(a1[bi], a1b[bi]), lo, hi);                          \
        h1n[bi] = tanh_scaled(lo + hi);          /* h1'(TT-1) */        \
    } while (0)

__global__ void __launch_bounds__(32, 13)
rnn2_kernel(const float* __restrict__ x,       // [B, T, 1]
            const float* __restrict__ hstate,  // [2, B, H]
            const float* __restrict__ Wih0,    // [H, 1]
            const float* __restrict__ Whh0,    // [H, H]
            const float* __restrict__ bih0, const float* __restrict__ bhh0,
            const float* __restrict__ Wih1,    // [H, H]
            const float* __restrict__ Whh1,    // [H, H]
            const float* __restrict__ bih1, const float* __restrict__ bhh1,
            const float* __restrict__ Wfc,     // [1, H]
            const float* __restrict__ bfc,     // [1]
            float* __restrict__ out)           // [B] pred ++ [2,B,H] h_new
{
    // Single-buffered per-batch h vectors. Every cross-halfstep hazard is
    // separated by one __syncwarp per halfstep; within a halfstep the two
    // batch streams touch disjoint buffers.
    __shared__ __align__(16) float sh0[2][HH];
    __shared__ __align__(16) float sh1[2][HH];

    const int j  = threadIdx.x;          // 0..31, one warp per block
    const int b0 = blockIdx.x * 2;       // two batch streams per warp

    const float SC = 2.885390081777927f; // 2*log2(e), folded into weights

    u64 w0[16], wi1[16], wh1[16];
    {
        const float2* p = (const float2*)(Whh0 + j * HH);
        #pragma unroll
        for (int i = 0; i < 16; i++) { float2 f = p[i]; w0[i]  = pk2(f.x*SC, f.y*SC); }
        p = (const float2*)(Wih1 + j * HH);
        #pragma unroll
        for (int i = 0; i < 16; i++) { float2 f = p[i]; wi1[i] = pk2(f.x*SC, f.y*SC); }
        p = (const float2*)(Whh1 + j * HH);
        #pragma unroll
        for (int i = 0; i < 16; i++) { float2 f = p[i]; wh1[i] = pk2(f.x*SC, f.y*SC); }
    }
    const float wx0 = Wih0[j] * SC;
    const float bb0 = (bih0[j] + bhh0[j]) * SC;
    const float bb1 = (bih1[j] + bhh1[j]) * SC;

    const float* xb[2];
    float xv[2];
    u64 a0[2], a0b[2], a1[2], a1b[2];
    float h1n[2];

    #pragma unroll
    for (int bi = 0; bi < 2; bi++) {
        sh0[bi][j] = hstate[(size_t)(b0 + bi) * HH + j];
        sh1[bi][j] = hstate[(size_t)BB * HH + (size_t)(b0 + bi) * HH + j];
        xb[bi] = x + (size_t)(b0 + bi) * TT;
    }
    __syncwarp();

    // ---- prologue: L0(0) for both batches -> sh0 ----
    #pragma unroll
    for (int bi = 0; bi < 2; bi++) {
        u64 a  = pk2(fmaf(wx0, xb[bi][0], bb0), 0.f);
        u64 ab = pk2(0.f, 0.f);
        #pragma unroll
        for (int i = 0; i < 8; i++) {
            ulonglong2 v = ((const ulonglong2*)sh0[bi])[i];
            a  = ffma2(w0[2*i],     v.x, a);
            ab = ffma2(w0[2*i + 1], v.y, ab);
        }
        float lo, hi;
        unpk2(fadd2(a, ab), lo, hi);
        float h = tanh_scaled(lo + hi);
        __syncwarp();                 // all lanes' reads done before write
        sh0[bi][j] = h;
        xv[bi] = xb[bi][1];
    }
    __syncwarp();

    // ---- skewed pipeline ----
    // HS-A0: compute b0 phase 0
    FFMA_FULL(0);  xv[0] = xb[0][2];
    __syncwarp();

    #pragma unroll 1
    for (int p = 0; p < TT - 2; p++) {
        // HS-B: compute b1 phase p  ||  finish b0 phase p
        FFMA_FULL(1);  xv[1] = xb[1][p + 2];
        FINISH_FULL(0);
        __syncwarp();
        // HS-A: compute b0 phase p+1  ||  finish b1 phase p
        FFMA_FULL(0);  xv[0] = xb[0][min(p + 3, TT - 1)];
        FINISH_FULL(1);
        __syncwarp();
    }
    // after loop: b0 computed phase TT-2, b1 finished through TT-3
    FFMA_FULL(1);                 // b1 phase TT-2 (xv[1] = x[TT-1])
    FINISH_FULL(0);               // b0 phase TT-2 -> sh0[0] = h0'(TT-1)
    __syncwarp();
    FFMA_L1(0);                   // b0 phase TT-1 (L1 only)
    FINISH_FULL(1);               // b1 phase TT-2 -> sh0[1] = h0'(TT-1)
    __syncwarp();
    FFMA_L1(1);                   // b1 phase TT-1 (L1 only)
    FINISH_L1(0);                 // h1n[0] = h1'(TT-1)
    __syncwarp();
    FINISH_L1(1);                 // h1n[1] = h1'(TT-1)

    // ---- outputs ----
    #pragma unroll
    for (int bi = 0; bi < 2; bi++) {
        const size_t ob = (size_t)(b0 + bi) * HH + j;
        out[BB + ob]                   = sh0[bi][j];  // h_new[0]
        out[BB + (size_t)BB * HH + ob] = h1n[bi];     // h_new[1]

        float p = Wfc[j] * h1n[bi];
        #pragma unroll
        for (int off = 16; off; off >>= 1)
            p += __shfl_xor_sync(0xffffffffu, p, off);
        if (j == 0) out[b0 + bi] = p + bfc[0];
    }
}

extern "C" void kernel_launch(void* const* d_in, const int* in_sizes, int n_in,
                              void* d_out, int out_size) {
    const float* x     = (const float*)d_in[0];
    const float* hs    = (const float*)d_in[1];
    const float* Wih0  = (const float*)d_in[2];
    const float* Whh0  = (const float*)d_in[3];
    const float* bih0  = (const float*)d_in[4];
    const float* bhh0  = (const float*)d_in[5];
    const float* Wih1  = (const float*)d_in[6];
    const float* Whh1  = (const float*)d_in[7];
    const float* bih1  = (const float*)d_in[8];
    const float* bhh1  = (const float*)d_in[9];
    const float* Wfc   = (const float*)d_in[10];
    const float* bfc   = (const float*)d_in[11];
    float* out = (float*)d_out;

    rnn2_kernel<<<BB / 2, 32>>>(x, hs, Wih0, Whh0, bih0, bhh0,
                                Wih1, Whh1, bih1, bhh1, Wfc, bfc, out);
}